// round 3
// baseline (speedup 1.0000x reference)
#include <cuda_runtime.h>
#include <cuda_bf16.h>

// Problem constants: T=2048, N=64, D=1024
#define T_DIM 2048
#define N_DIM 64
#define D_DIM 1024
#define D_VEC (D_DIM / 4)          // 256 float4 per row
#define VEC_PER_LANE 8             // 256 / 32 lanes
#define C_CHUNKS 64                // t ≡ c (mod 64)
#define WARPS_PER_BLOCK 8
#define ROWS_PER_WARP 4            // 8 warps * 4 rows = 32 rows = all j in [0,32)
#define HALF_LOG_2PI 0.91893853320467274178f
#define EPS_VAR 1e-6f

__global__ void zero_out_kernel(float* __restrict__ out) {
    if (threadIdx.x < N_DIM) out[threadIdx.x] = 0.0f;
}

__global__ __launch_bounds__(WARPS_PER_BLOCK * 32)
void gnll_kernel(const float* __restrict__ y,     // (T, N)
                 const float4* __restrict__ x4,   // (T, N, D/4)
                 const float4* __restrict__ W4,   // (2, D/4)
                 const int* __restrict__ lens,    // (N,)
                 float* __restrict__ out)         // (N,)
{
    const int n    = blockIdx.y;
    const int c    = blockIdx.x;          // t ≡ c (mod 64)
    const int len  = lens[n];
    const int wid  = threadIdx.x >> 5;
    const int lane = threadIdx.x & 31;

    __shared__ float s_partial[WARPS_PER_BLOCK];

    // Row assignment: t = c + 64*(wid*4 + r), r in [0,4). All t < 2048.
    int  tr[ROWS_PER_WARP];
    bool vr[ROWS_PER_WARP];
    #pragma unroll
    for (int r = 0; r < ROWS_PER_WARP; r++) {
        tr[r] = c + C_CHUNKS * (wid * ROWS_PER_WARP + r);
        vr[r] = tr[r] < len;
    }

    float warp_sum = 0.0f;

    if (vr[0]) {  // valid rows are a prefix in r; if none, skip all x traffic
        // Preload W lane-striped (matches x access pattern). 64 regs.
        float4 w0[VEC_PER_LANE], w1[VEC_PER_LANE];
        #pragma unroll
        for (int i = 0; i < VEC_PER_LANE; i++) {
            w0[i] = W4[i * 32 + lane];
            w1[i] = W4[D_VEC + i * 32 + lane];
        }

        const float4* rowp[ROWS_PER_WARP];
        #pragma unroll
        for (int r = 0; r < ROWS_PER_WARP; r++)
            rowp[r] = x4 + ((size_t)tr[r] * N_DIM + n) * D_VEC;

        float a0[ROWS_PER_WARP], a1[ROWS_PER_WARP];
        #pragma unroll
        for (int r = 0; r < ROWS_PER_WARP; r++) { a0[r] = 0.0f; a1[r] = 0.0f; }

        // Interleave loads across the 4 rows: up to 32 predicated LDG.128
        // outstanding per lane across the unrolled i-loop.
        #pragma unroll
        for (int i = 0; i < VEC_PER_LANE; i++) {
            float4 v[ROWS_PER_WARP];
            #pragma unroll
            for (int r = 0; r < ROWS_PER_WARP; r++) {
                v[r] = make_float4(0.f, 0.f, 0.f, 0.f);
                if (vr[r]) v[r] = rowp[r][i * 32 + lane];
            }
            #pragma unroll
            for (int r = 0; r < ROWS_PER_WARP; r++) {
                a0[r] = fmaf(v[r].x, w0[i].x, a0[r]);
                a0[r] = fmaf(v[r].y, w0[i].y, a0[r]);
                a0[r] = fmaf(v[r].z, w0[i].z, a0[r]);
                a0[r] = fmaf(v[r].w, w0[i].w, a0[r]);
                a1[r] = fmaf(v[r].x, w1[i].x, a1[r]);
                a1[r] = fmaf(v[r].y, w1[i].y, a1[r]);
                a1[r] = fmaf(v[r].z, w1[i].z, a1[r]);
                a1[r] = fmaf(v[r].w, w1[i].w, a1[r]);
            }
        }

        // 8 independent butterfly chains — latencies overlap.
        #pragma unroll
        for (int off = 16; off > 0; off >>= 1) {
            #pragma unroll
            for (int r = 0; r < ROWS_PER_WARP; r++) {
                a0[r] += __shfl_xor_sync(0xFFFFFFFFu, a0[r], off);
                a1[r] += __shfl_xor_sync(0xFFFFFFFFu, a1[r], off);
            }
        }

        if (lane == 0) {
            #pragma unroll
            for (int r = 0; r < ROWS_PER_WARP; r++) {
                if (vr[r]) {
                    float mu  = a0[r];
                    float var = 1.0f / (1.0f + __expf(-a1[r]));   // sigmoid
                    var = fmaxf(var, EPS_VAR);
                    float d = y[tr[r] * N_DIM + n] - mu;
                    warp_sum += 0.5f * (__logf(var) + d * d / var) + HALF_LOG_2PI;
                }
            }
        }
    }

    if (lane == 0) s_partial[wid] = warp_sum;
    __syncthreads();
    if (threadIdx.x == 0) {
        float s = 0.0f;
        #pragma unroll
        for (int i = 0; i < WARPS_PER_BLOCK; i++) s += s_partial[i];
        if (s != 0.0f) atomicAdd(&out[n], s);
    }
}

extern "C" void kernel_launch(void* const* d_in, const int* in_sizes, int n_in,
                              void* d_out, int out_size) {
    // metadata order: y (T*N f32), x (T*N*D f32), W (2*D f32), lens (N i32)
    const float*  y    = (const float*)d_in[0];
    const float4* x4   = (const float4*)d_in[1];
    const float4* W4   = (const float4*)d_in[2];
    const int*    lens = (const int*)d_in[3];
    float*        out  = (float*)d_out;

    zero_out_kernel<<<1, 64>>>(out);

    dim3 grid(C_CHUNKS, N_DIM);
    dim3 block(WARPS_PER_BLOCK * 32);
    gnll_kernel<<<grid, block>>>(y, x4, W4, lens, out);
}

// round 8
// speedup vs baseline: 1.5902x; 1.5902x over previous
#include <cuda_runtime.h>
#include <cuda_bf16.h>
#include <cstdint>

// Problem constants: T=2048, N=64, D=1024
#define T_DIM 2048
#define N_DIM 64
#define D_DIM 1024
#define D_VEC 256                 // float4 per row
#define VEC_PER_LANE 8            // 256 / 32 lanes
#define TILE_T 4                  // rows per tile (= warps per block)
#define NBX 32                    // blocks per sequence (strided tile ownership)
#define NWARPS 4
#define NTHREADS 128
#define CHUNKS_PER_THREAD ((TILE_T * D_VEC) / NTHREADS)   // 8 x 16B per thread
#define HALF_LOG_2PI 0.91893853320467274178f
#define EPS_VAR 1e-6f

__global__ void zero_out_kernel(float* __restrict__ out) {
    if (threadIdx.x < N_DIM) out[threadIdx.x] = 0.0f;
}

__device__ __forceinline__ void cp_async16(unsigned int saddr, const void* gptr) {
    asm volatile("cp.async.cg.shared.global [%0], [%1], 16;\n"
                 :: "r"(saddr), "l"(gptr));
}
__device__ __forceinline__ void cp_commit() {
    asm volatile("cp.async.commit_group;\n" ::: "memory");
}
__device__ __forceinline__ void cp_wait1() {
    asm volatile("cp.async.wait_group 1;\n" ::: "memory");
}

__global__ __launch_bounds__(NTHREADS, 4)
void gnll_kernel(const float* __restrict__ y,     // (T, N)
                 const float4* __restrict__ x4,   // (T, N, D/4)
                 const float4* __restrict__ W4,   // (2, D/4)
                 const int* __restrict__ lens,    // (N,)
                 float* __restrict__ out)         // (N,)
{
    __shared__ float4 buf[2][TILE_T * D_VEC];     // 2 x 16KB
    __shared__ float  s_partial[NWARPS];

    const int n    = blockIdx.y;
    const int bx   = blockIdx.x;
    const int len  = lens[n];
    const int tid  = threadIdx.x;
    const int wid  = tid >> 5;
    const int lane = tid & 31;

    // Tiles owned by this block: j = bx + k*NBX, rows [j*TILE_T, (j+1)*TILE_T)
    int kmax = 0;
    {
        int jlim = (len + TILE_T - 1) / TILE_T;   // tiles containing any valid row
        if (bx < jlim) kmax = (jlim - bx + NBX - 1) / NBX;
    }
    if (kmax == 0) return;

    // Preload W lane-striped into registers (64 regs; launch_bounds grants 128).
    float4 w0[VEC_PER_LANE], w1[VEC_PER_LANE];
    #pragma unroll
    for (int i = 0; i < VEC_PER_LANE; i++) {
        w0[i] = W4[i * 32 + lane];
        w1[i] = W4[D_VEC + i * 32 + lane];
    }

    // Issue one tile's cp.asyncs (skipping rows >= len) and commit a group.
    // All threads execute this uniformly: exactly one commit_group per call.
    auto issue_tile = [&](int k, int stage) {
        const int t0 = (bx + k * NBX) * TILE_T;
        unsigned int sbase = (unsigned int)__cvta_generic_to_shared(&buf[stage][0]);
        #pragma unroll
        for (int c = 0; c < CHUNKS_PER_THREAD; c++) {
            int idx = tid + c * NTHREADS;          // 0..1023 float4 slots
            int t   = t0 + (idx >> 8);             // row within tile
            if (t < len) {
                const float4* g = x4 + ((size_t)t * N_DIM + n) * D_VEC + (idx & 255);
                cp_async16(sbase + (unsigned int)idx * 16u, g);
            }
        }
        cp_commit();
    };

    // Prologue: always commit exactly 2 groups.
    issue_tile(0, 0);
    if (kmax > 1) issue_tile(1, 1); else cp_commit();

    float warp_sum = 0.0f;

    for (int k = 0; k < kmax; k++) {
        // Invariant: tile k's group + exactly one newer group are pending.
        cp_wait1();
        __syncthreads();

        const int stage = k & 1;
        const int t = (bx + k * NBX) * TILE_T + wid;   // this warp's row
        if (t < len) {
            const float4* src = &buf[stage][wid * D_VEC];
            float a0 = 0.0f, a1 = 0.0f;
            #pragma unroll
            for (int i = 0; i < VEC_PER_LANE; i++) {
                float4 v = src[i * 32 + lane];
                a0 = fmaf(v.x, w0[i].x, a0);
                a0 = fmaf(v.y, w0[i].y, a0);
                a0 = fmaf(v.z, w0[i].z, a0);
                a0 = fmaf(v.w, w0[i].w, a0);
                a1 = fmaf(v.x, w1[i].x, a1);
                a1 = fmaf(v.y, w1[i].y, a1);
                a1 = fmaf(v.z, w1[i].z, a1);
                a1 = fmaf(v.w, w1[i].w, a1);
            }
            #pragma unroll
            for (int off = 16; off > 0; off >>= 1) {
                a0 += __shfl_xor_sync(0xFFFFFFFFu, a0, off);
                a1 += __shfl_xor_sync(0xFFFFFFFFu, a1, off);
            }
            if (lane == 0) {
                float mu  = a0;
                float var = fmaxf(1.0f / (1.0f + __expf(-a1)), EPS_VAR);
                float d   = y[t * N_DIM + n] - mu;
                warp_sum += 0.5f * (__logf(var) + d * d / var) + HALF_LOG_2PI;
            }
        }
        __syncthreads();   // all warps done reading this stage

        // Refill consumed stage; exactly one commit per iteration, uniformly.
        if (k + 2 < kmax) issue_tile(k + 2, stage); else cp_commit();
    }

    if (lane == 0) s_partial[wid] = warp_sum;
    __syncthreads();
    if (tid == 0) {
        float s = s_partial[0] + s_partial[1] + s_partial[2] + s_partial[3];
        atomicAdd(&out[n], s);
    }
}

extern "C" void kernel_launch(void* const* d_in, const int* in_sizes, int n_in,
                              void* d_out, int out_size) {
    // metadata order: y (T*N f32), x (T*N*D f32), W (2*D f32), lens (N i32)
    const float*  y    = (const float*)d_in[0];
    const float4* x4   = (const float4*)d_in[1];
    const float4* W4   = (const float4*)d_in[2];
    const int*    lens = (const int*)d_in[3];
    float*        out  = (float*)d_out;

    zero_out_kernel<<<1, 64>>>(out);

    dim3 grid(NBX, N_DIM);
    dim3 block(NTHREADS);
    gnll_kernel<<<grid, block>>>(y, x4, W4, lens, out);
}